// round 16
// baseline (speedup 1.0000x reference)
#include <cuda_runtime.h>
#include <cuda_fp16.h>
#include <math.h>
#include <stdint.h>
#include <mma.h>

using namespace nvcuda;

// ---------------------------------------------------------------------------
// RGCN, GEMM-first + CSR gather.
//   z_r = xr @ W1r_r (tf32 pre-rounded, raw-bit staged) -> fp16 z
//   h[d] = tf32round(relu(sum_e coef*z[...] + b1sum))   (fp32 h, pre-rounded)
//   y_r = h @ W2r_r -> fp16 y ; out[d] = sum_e coef*y[...] + b2sum
// ---------------------------------------------------------------------------

#define NREL 4
#define INF  128
#define HF   128
#define OUTF 64
#define MAXN 100000
#define MAXE 400000
#define MAXT ((MAXN + 127) / 128)
#define MAXP (MAXT * 128)
#define SCAN_B 1024

__device__ __half g_z[(size_t)NREL * MAXP * HF];
__device__ __half g_y[(size_t)NREL * MAXP * OUTF];
__device__ float  g_h[(size_t)MAXN * HF];
__device__ float  g_xr[(size_t)MAXN * INF];
__device__ float  g_w1r[NREL * 128 * HF];
__device__ float  g_w2r[NREL * 128 * OUTF];
__device__ float  g_deg_src[NREL * MAXN];
__device__ float  g_deg_dst[NREL * MAXN];
__device__ int    g_cnt[MAXN + 1];
__device__ int    g_off[MAXN + 1];
__device__ int    g_cursor[MAXN];
__device__ int    g_bsum[128];
__device__ int    g_boff[128];
__device__ int2   g_edge[NREL * MAXE];  // .x = src | rel<<20, .y = coef bits
__device__ int    g_idx64;

__device__ __forceinline__ int load_idx(const void* p, size_t i, int is64) {
    return is64 ? (int)((const long long*)p)[i] : ((const int*)p)[i];
}

__device__ __forceinline__ void cp16(void* smem, const void* gmem, int src_sz) {
    uint32_t d = (uint32_t)__cvta_generic_to_shared(smem);
    asm volatile("cp.async.cg.shared.global [%0], [%1], 16, %2;"
                 :: "r"(d), "l"(gmem), "r"(src_sz) : "memory");
}
__device__ __forceinline__ void cp16(void* smem, const void* gmem) {
    uint32_t d = (uint32_t)__cvta_generic_to_shared(smem);
    asm volatile("cp.async.cg.shared.global [%0], [%1], 16;"
                 :: "r"(d), "l"(gmem) : "memory");
}
#define CP_COMMIT() asm volatile("cp.async.commit_group;" ::: "memory")
#define CP_WAIT(n)  asm volatile("cp.async.wait_group %0;" :: "n"(n) : "memory")

// ---------------------------------------------------------------------------
__global__ void init_kernel(const unsigned int* __restrict__ words, int n_words,
                            float* __restrict__ ds, float* __restrict__ dd, int nrs,
                            int* __restrict__ cnt, int* __restrict__ cur, int n) {
    if (blockIdx.x == 0) {
        int limit = n_words < 4096 ? n_words : 4096;
        int bad = 0;
        for (int i = 1 + 2 * (int)threadIdx.x; i < limit; i += 2 * (int)blockDim.x)
            bad |= (words[i] != 0u);
        bad = __syncthreads_or(bad);
        if (threadIdx.x == 0) g_idx64 = bad ? 0 : 1;
    }
    int i = blockIdx.x * blockDim.x + threadIdx.x;
    int st = gridDim.x * blockDim.x;
    for (int k = i; k < nrs; k += st) { ds[k] = 0.0f; dd[k] = 0.0f; }
    for (int k = i; k < n; k += st)   { cnt[k] = 0; cur[k] = 0; }
}

// round x to tf32 (RN) into xr
__global__ void roundx_kernel(const float* __restrict__ X, float* __restrict__ XR,
                              size_t n4) {
    size_t i = (size_t)blockIdx.x * blockDim.x + threadIdx.x;
    size_t st = (size_t)gridDim.x * blockDim.x;
    for (; i < n4; i += st) {
        float4 v = ((const float4*)X)[i];
        v.x = wmma::__float_to_tf32(v.x);
        v.y = wmma::__float_to_tf32(v.y);
        v.z = wmma::__float_to_tf32(v.z);
        v.w = wmma::__float_to_tf32(v.w);
        ((float4*)XR)[i] = v;
    }
}

__global__ void roundw_kernel(const float* __restrict__ W1, const float* __restrict__ W2,
                              float* __restrict__ W1R, float* __restrict__ W2R) {
    int i = blockIdx.x * blockDim.x + threadIdx.x;
    if (i < NREL * 128 * HF)   W1R[i] = wmma::__float_to_tf32(W1[i]);
    if (i < NREL * 128 * OUTF) W2R[i] = wmma::__float_to_tf32(W2[i]);
}

__global__ void degree_kernel(const void* __restrict__ src, const void* __restrict__ dst,
                              float* __restrict__ ds, float* __restrict__ dd,
                              int* __restrict__ cnt, int E, int M) {
    int i = blockIdx.x * blockDim.x + threadIdx.x;
    if (i >= NREL * E) return;
    const int is64 = g_idx64;
    int r = i / E;
    int s = load_idx(src, i, is64);
    int d = load_idx(dst, i, is64);
    atomicAdd(&ds[r * M + s], 1.0f);
    atomicAdd(&dd[r * M + d], 1.0f);
    atomicAdd(&cnt[d], 1);
}

// ---------------------------------------------------------------------------
__device__ __forceinline__ int block_incl_scan(int v, int* wsum) {
    const int lane = threadIdx.x & 31, wid = threadIdx.x >> 5;
    int s = v;
#pragma unroll
    for (int o = 1; o < 32; o <<= 1) {
        int t = __shfl_up_sync(~0u, s, o);
        if (lane >= o) s += t;
    }
    if (lane == 31) wsum[wid] = s;
    __syncthreads();
    if (wid == 0) {
        int ws = (lane < (SCAN_B / 32)) ? wsum[lane] : 0;
#pragma unroll
        for (int o = 1; o < 32; o <<= 1) {
            int t = __shfl_up_sync(~0u, ws, o);
            if (lane >= o) ws += t;
        }
        wsum[lane] = ws;
    }
    __syncthreads();
    return s + (wid > 0 ? wsum[wid - 1] : 0);
}

__global__ void scanA_kernel(const int* __restrict__ cnt, int* __restrict__ bsum, int n) {
    __shared__ int wsum[32];
    int i = blockIdx.x * SCAN_B + threadIdx.x;
    int v = (i < n) ? cnt[i] : 0;
    int s = block_incl_scan(v, wsum);
    if (threadIdx.x == SCAN_B - 1) bsum[blockIdx.x] = s;
}

__global__ void scanB_kernel(const int* __restrict__ bsum, int* __restrict__ boff,
                             int* __restrict__ off, int nb, int n) {
    const int lane = threadIdx.x;
    int carry = 0;
    for (int base = 0; base < nb; base += 32) {
        int i = base + lane;
        int v = (i < nb) ? bsum[i] : 0;
        int s = v;
#pragma unroll
        for (int o = 1; o < 32; o <<= 1) {
            int t = __shfl_up_sync(~0u, s, o);
            if (lane >= o) s += t;
        }
        if (i < nb) boff[i] = carry + s - v;
        carry += __shfl_sync(~0u, s, 31);
    }
    if (lane == 0) off[n] = carry;
}

__global__ void scanC_kernel(const int* __restrict__ cnt, const int* __restrict__ boff,
                             int* __restrict__ off, int n) {
    __shared__ int wsum[32];
    int i = blockIdx.x * SCAN_B + threadIdx.x;
    int v = (i < n) ? cnt[i] : 0;
    int s = block_incl_scan(v, wsum);
    if (i < n) off[i] = boff[blockIdx.x] + s - v;
}

// ---------------------------------------------------------------------------
__global__ void fill_kernel(const void* __restrict__ src, const void* __restrict__ dst,
                            const float* __restrict__ ds, const float* __restrict__ dd,
                            const int* __restrict__ off, int* __restrict__ cur,
                            int2* __restrict__ edge, int E, int M) {
    int i = blockIdx.x * blockDim.x + threadIdx.x;
    if (i >= NREL * E) return;
    const int is64 = g_idx64;
    int r = i / E;
    int s = load_idx(src, i, is64);
    int d = load_idx(dst, i, is64);
    int pos = off[d] + atomicAdd(&cur[d], 1);
    float coef = rsqrtf(fmaxf(ds[r * M + s], 1.0f)) *
                 rsqrtf(fmaxf(dd[r * M + d], 1.0f));
    edge[pos] = make_int2(s | (r << 20), __float_as_int(coef));
}

// ---------------------------------------------------------------------------
// wmma tf32 GEMM. Inputs pre-rounded to tf32 -> raw-bit staging (cp.async),
// no in-fragment rounding. Output converted to fp16 via warp-private SMEM.
// ---------------------------------------------------------------------------
template <int NF>
__global__ __launch_bounds__(256, 2)
void gemm_kernel(const float* __restrict__ A, const float* __restrict__ B,
                 __half* __restrict__ C, int M, int Mp) {
    constexpr int NFRAG = NF / 32;
    constexpr int AST = 36, BST = NF + 4;
    constexpr int ABUF = 128 * AST, BBUF = 32 * BST;
    constexpr int BCH = (32 * NF / 4) / 256;
    constexpr int EST = NF / 2 + 4;          // epilogue staging stride
    constexpr int H2R = NF / 4;              // half2 slots per warp-row
    extern __shared__ float sm[];
    float* As = sm;
    float* Bs = sm + 2 * ABUF;

    const int r    = blockIdx.y;
    const int row0 = blockIdx.x * 128;
    const int tid  = threadIdx.x;
    const int wid  = tid >> 5;
    const int lane = tid & 31;
    const int wm   = wid >> 1;
    const int wn   = wid & 1;
    const float* Br = B + (size_t)r * 128 * NF;

    const int arr = tid >> 1;
    const int acb = (tid & 1) * 16;
    const int gr  = row0 + arr;
    const int asz = (gr < M) ? 16 : 0;
    const float* Arow = A + (size_t)gr * 128 + acb;

    auto stage = [&](int kc, int buf) {
        float* Ab = As + buf * ABUF + arr * AST + acb;
        const float* Ag = Arow + kc * 32;
#pragma unroll
        for (int j = 0; j < 4; j++)
            cp16(Ab + j * 4, Ag + j * 4, asz);
#pragma unroll
        for (int i = 0; i < BCH; i++) {
            int idx = tid + i * 256;
            int rr = idx / (NF / 4);
            int cc = (idx % (NF / 4)) * 4;
            cp16(Bs + buf * BBUF + rr * BST + cc,
                 Br + (size_t)(kc * 32 + rr) * NF + cc);
        }
        CP_COMMIT();
    };

    wmma::fragment<wmma::accumulator, 16, 16, 8, float> acc[2][NFRAG];
#pragma unroll
    for (int m = 0; m < 2; m++)
#pragma unroll
        for (int n = 0; n < NFRAG; n++) wmma::fill_fragment(acc[m][n], 0.0f);

    stage(0, 0);
#pragma unroll
    for (int kc = 0; kc < 4; kc++) {
        const int cur = kc & 1;
        if (kc < 3) {
            stage(kc + 1, cur ^ 1);
            CP_WAIT(1);
        } else {
            CP_WAIT(0);
        }
        __syncthreads();
        const float* Ab = As + cur * ABUF + (wm * 32) * AST;
        const float* Bb = Bs + cur * BBUF + wn * (NF / 2);
#pragma unroll
        for (int kf = 0; kf < 4; kf++) {
            wmma::fragment<wmma::matrix_a, 16, 16, 8, wmma::precision::tf32,
                           wmma::row_major> a0, a1;
            wmma::load_matrix_sync(a0, Ab + kf * 8, AST);
            wmma::load_matrix_sync(a1, Ab + 16 * AST + kf * 8, AST);
#pragma unroll
            for (int n = 0; n < NFRAG; n++) {
                wmma::fragment<wmma::matrix_b, 16, 16, 8, wmma::precision::tf32,
                               wmma::row_major> b;
                wmma::load_matrix_sync(b, Bb + (kf * 8) * BST + n * 16, BST);
                wmma::mma_sync(acc[0][n], a0, b, acc[0][n]);
                wmma::mma_sync(acc[1][n], a1, b, acc[1][n]);
            }
        }
        __syncthreads();
    }

    // epilogue: frags -> warp-private SMEM -> fp16 coalesced stores.
    // Each warp owns 32 rows x NF/2 floats; per row = NF/4 half2 slots.
    float* Wst = sm + wid * 32 * EST;
#pragma unroll
    for (int m = 0; m < 2; m++)
#pragma unroll
        for (int n = 0; n < NFRAG; n++)
            wmma::store_matrix_sync(Wst + m * 16 * EST + n * 16, acc[m][n],
                                    EST, wmma::mem_row_major);
    __syncwarp();
    if (lane < H2R) {
#pragma unroll 4
        for (int rr = 0; rr < 32; rr++) {
            float2 v = *(float2*)(Wst + rr * EST + lane * 2);
            __half2* dst = (__half2*)(C + ((size_t)r * Mp + row0 + wm * 32 + rr) * NF
                                        + wn * (NF / 2));
            dst[lane] = __floats2half2_rn(v.x, v.y);
        }
    }
}

// ---------------------------------------------------------------------------
// gather1: warp per dst, 128 feats (fp16 z); h = tf32round(relu(agg + b1sum))
__global__ __launch_bounds__(256)
void gather1_kernel(const __half2* __restrict__ Z, const int* __restrict__ off,
                    const int2* __restrict__ edge,
                    const float* __restrict__ b1, float* __restrict__ h,
                    int M, int Mp) {
    const int d = blockIdx.x * 8 + (threadIdx.x >> 5);
    const int lane = threadIdx.x & 31;
    if (d >= M) return;
    const int e0 = off[d], e1 = off[d + 1];
    float4 acc = make_float4(0.f, 0.f, 0.f, 0.f);
#pragma unroll 8
    for (int e = e0; e < e1; e++) {
        const int2 ed = __ldg(&edge[e]);
        const int s = ed.x & 0xFFFFF, r = ed.x >> 20;
        const float c = __int_as_float(ed.y);
        const __half2* zrow = Z + ((size_t)r * Mp + s) * 64 + lane * 2;
        const uint2 u = __ldg((const uint2*)zrow);
        float2 f0 = __half22float2(*(const __half2*)&u.x);
        float2 f1 = __half22float2(*(const __half2*)&u.y);
        acc.x += c * f0.x; acc.y += c * f0.y;
        acc.z += c * f1.x; acc.w += c * f1.y;
    }
    const int f = lane * 4;
    float4 o;
    o.x = wmma::__float_to_tf32(fmaxf(acc.x + b1[f+0] + b1[128+f+0] + b1[256+f+0] + b1[384+f+0], 0.f));
    o.y = wmma::__float_to_tf32(fmaxf(acc.y + b1[f+1] + b1[128+f+1] + b1[256+f+1] + b1[384+f+1], 0.f));
    o.z = wmma::__float_to_tf32(fmaxf(acc.z + b1[f+2] + b1[128+f+2] + b1[256+f+2] + b1[384+f+2], 0.f));
    o.w = wmma::__float_to_tf32(fmaxf(acc.w + b1[f+3] + b1[128+f+3] + b1[256+f+3] + b1[384+f+3], 0.f));
    *(float4*)(h + (size_t)d * 128 + f) = o;
}

// gather2: half-warp per dst, 64 feats (fp16 y); out = agg + b2sum
__global__ __launch_bounds__(256)
void gather2_kernel(const __half2* __restrict__ Y, const int* __restrict__ off,
                    const int2* __restrict__ edge,
                    const float* __restrict__ b2, float* __restrict__ out,
                    int M, int Mp) {
    const int warp = blockIdx.x * 8 + (threadIdx.x >> 5);
    const int lane = threadIdx.x & 31;
    const int d = warp * 2 + (lane >> 4);
    const int fl = lane & 15;
    if (d >= M) return;
    const int e0 = off[d], e1 = off[d + 1];
    float4 acc = make_float4(0.f, 0.f, 0.f, 0.f);
#pragma unroll 8
    for (int e = e0; e < e1; e++) {
        const int2 ed = __ldg(&edge[e]);
        const int s = ed.x & 0xFFFFF, r = ed.x >> 20;
        const float c = __int_as_float(ed.y);
        const __half2* yrow = Y + ((size_t)r * Mp + s) * 32 + fl * 2;
        const uint2 u = __ldg((const uint2*)yrow);
        float2 f0 = __half22float2(*(const __half2*)&u.x);
        float2 f1 = __half22float2(*(const __half2*)&u.y);
        acc.x += c * f0.x; acc.y += c * f0.y;
        acc.z += c * f1.x; acc.w += c * f1.y;
    }
    const int f = fl * 4;
    float4 o;
    o.x = acc.x + b2[f+0] + b2[64+f+0] + b2[128+f+0] + b2[192+f+0];
    o.y = acc.y + b2[f+1] + b2[64+f+1] + b2[128+f+1] + b2[192+f+1];
    o.z = acc.z + b2[f+2] + b2[64+f+2] + b2[128+f+2] + b2[192+f+2];
    o.w = acc.w + b2[f+3] + b2[64+f+3] + b2[128+f+3] + b2[192+f+3];
    *(float4*)(out + (size_t)d * 64 + f) = o;
}

// ---------------------------------------------------------------------------
extern "C" void kernel_launch(void* const* d_in, const int* in_sizes, int n_in,
                              void* d_out, int out_size) {
    const float* x    = (const float*)d_in[0];
    const void*  srcI = d_in[1];
    const void*  dstI = d_in[2];
    const float* W1   = (const float*)d_in[3];
    const float* b1   = (const float*)d_in[4];
    const float* W2   = (const float*)d_in[5];
    const float* b2   = (const float*)d_in[6];
    float*       out  = (float*)d_out;

    const int M = in_sizes[0] / INF;
    const int E = in_sizes[1] / NREL;
    const int tiles = (M + 127) / 128;
    const int Mp = tiles * 128;
    const int NB = (M + SCAN_B - 1) / SCAN_B;

    __half *z, *y;
    float *h, *xr, *w1r, *w2r, *ds, *dd;
    int *cnt, *off, *cur, *bsum, *boff;
    int2 *edge;
    cudaGetSymbolAddress((void**)&z, g_z);
    cudaGetSymbolAddress((void**)&y, g_y);
    cudaGetSymbolAddress((void**)&h, g_h);
    cudaGetSymbolAddress((void**)&xr, g_xr);
    cudaGetSymbolAddress((void**)&w1r, g_w1r);
    cudaGetSymbolAddress((void**)&w2r, g_w2r);
    cudaGetSymbolAddress((void**)&ds, g_deg_src);
    cudaGetSymbolAddress((void**)&dd, g_deg_dst);
    cudaGetSymbolAddress((void**)&cnt, g_cnt);
    cudaGetSymbolAddress((void**)&off, g_off);
    cudaGetSymbolAddress((void**)&cur, g_cursor);
    cudaGetSymbolAddress((void**)&edge, g_edge);
    cudaGetSymbolAddress((void**)&bsum, g_bsum);
    cudaGetSymbolAddress((void**)&boff, g_boff);

    const int SMEM1 = (2 * 128 * 36 + 2 * 32 * (HF + 4)) * 4;    // 70656
    const int SMEM2 = (2 * 128 * 36 + 2 * 32 * (OUTF + 4)) * 4;  // 54272
    cudaFuncSetAttribute(gemm_kernel<HF>,
                         cudaFuncAttributeMaxDynamicSharedMemorySize, SMEM1);
    cudaFuncSetAttribute(gemm_kernel<OUTF>,
                         cudaFuncAttributeMaxDynamicSharedMemorySize, SMEM2);

    // 1 init (+detect)
    init_kernel<<<512, 256>>>((const unsigned int*)srcI, NREL * E,
                              ds, dd, NREL * M, cnt, cur, M);
    // 2 round x -> xr (tf32 RN)
    roundx_kernel<<<2048, 256>>>(x, xr, (size_t)M * INF / 4);
    // 3 round weights
    roundw_kernel<<<(NREL * 128 * HF + 255) / 256, 256>>>(W1, W2, w1r, w2r);
    // 4 layer-1 GEMM (ncu capture slot)
    {
        dim3 grid(tiles, NREL);
        gemm_kernel<HF><<<grid, 256, SMEM1>>>(xr, w1r, z, M, Mp);
    }
    // 5 degrees + counts
    degree_kernel<<<(NREL * E + 255) / 256, 256>>>(srcI, dstI, ds, dd, cnt, E, M);
    // 6-8 scan
    scanA_kernel<<<NB, SCAN_B>>>(cnt, bsum, M);
    scanB_kernel<<<1, 32>>>(bsum, boff, off, NB, M);
    scanC_kernel<<<NB, SCAN_B>>>(cnt, boff, off, M);
    // 9 fill CSR
    fill_kernel<<<(NREL * E + 255) / 256, 256>>>(srcI, dstI, ds, dd,
                                                 off, cur, edge, E, M);
    // 10 layer-1 gather (+bias+relu+tf32 round)
    gather1_kernel<<<(M + 7) / 8, 256>>>((const __half2*)z, off, edge, b1, h, M, Mp);
    // 11 layer-2 GEMM
    {
        dim3 grid(tiles, NREL);
        gemm_kernel<OUTF><<<grid, 256, SMEM2>>>(h, w2r, y, M, Mp);
    }
    // 12 layer-2 gather (+bias)
    gather2_kernel<<<(M + 15) / 16, 256>>>((const __half2*)y, off, edge, b2, out, M, Mp);
}

// round 17
// speedup vs baseline: 1.7486x; 1.7486x over previous
#include <cuda_runtime.h>
#include <cuda_bf16.h>
#include <math.h>
#include <stdint.h>
#include <mma.h>

using namespace nvcuda;

// ---------------------------------------------------------------------------
// RGCN, GEMM-first + CSR gather. wmma tf32 GEMM, 128x128 CTA tile, warp tile
// 32x(NF/2), KC=32 double-buffered cp.async. Inputs PRE-ROUNDED to tf32 (RN)
// so raw-bit staging + HW truncation is exact; no in-fragment rounding.
// z/y scratch fp32 (fp16 scratch caused 9x DRAM amplification in R16).
//   z_r = xr @ W1r_r ; h[d] = tf32round(relu(sum_e coef*z[...] + b1sum))
//   y_r = h @ W2r_r  ; out[d] = sum_e coef*y[...] + b2sum
// ---------------------------------------------------------------------------

#define NREL 4
#define INF  128
#define HF   128
#define OUTF 64
#define MAXN 100000
#define MAXE 400000
#define MAXT ((MAXN + 127) / 128)
#define MAXP (MAXT * 128)
#define SCAN_B 1024

__device__ float g_z[(size_t)NREL * MAXP * HF];
__device__ float g_y[(size_t)NREL * MAXP * OUTF];
__device__ float g_h[(size_t)MAXN * HF];
__device__ float g_xr[(size_t)MAXN * INF];
__device__ float g_w1r[NREL * 128 * HF];
__device__ float g_w2r[NREL * 128 * OUTF];
__device__ float g_deg_src[NREL * MAXN];
__device__ float g_deg_dst[NREL * MAXN];
__device__ int   g_cnt[MAXN + 1];
__device__ int   g_off[MAXN + 1];
__device__ int   g_cursor[MAXN];
__device__ int   g_bsum[128];
__device__ int   g_boff[128];
__device__ int2  g_edge[NREL * MAXE];   // .x = src | rel<<20, .y = coef bits
__device__ int   g_idx64;

__device__ __forceinline__ int load_idx(const void* p, size_t i, int is64) {
    return is64 ? (int)((const long long*)p)[i] : ((const int*)p)[i];
}

__device__ __forceinline__ void cp16(void* smem, const void* gmem, int src_sz) {
    uint32_t d = (uint32_t)__cvta_generic_to_shared(smem);
    asm volatile("cp.async.cg.shared.global [%0], [%1], 16, %2;"
                 :: "r"(d), "l"(gmem), "r"(src_sz) : "memory");
}
__device__ __forceinline__ void cp16(void* smem, const void* gmem) {
    uint32_t d = (uint32_t)__cvta_generic_to_shared(smem);
    asm volatile("cp.async.cg.shared.global [%0], [%1], 16;"
                 :: "r"(d), "l"(gmem) : "memory");
}
#define CP_COMMIT() asm volatile("cp.async.commit_group;" ::: "memory")
#define CP_WAIT(n)  asm volatile("cp.async.wait_group %0;" :: "n"(n) : "memory")

// ---------------------------------------------------------------------------
__global__ void init_kernel(const unsigned int* __restrict__ words, int n_words,
                            float* __restrict__ ds, float* __restrict__ dd, int nrs,
                            int* __restrict__ cnt, int* __restrict__ cur, int n) {
    if (blockIdx.x == 0) {
        int limit = n_words < 4096 ? n_words : 4096;
        int bad = 0;
        for (int i = 1 + 2 * (int)threadIdx.x; i < limit; i += 2 * (int)blockDim.x)
            bad |= (words[i] != 0u);
        bad = __syncthreads_or(bad);
        if (threadIdx.x == 0) g_idx64 = bad ? 0 : 1;
    }
    int i = blockIdx.x * blockDim.x + threadIdx.x;
    int st = gridDim.x * blockDim.x;
    for (int k = i; k < nrs; k += st) { ds[k] = 0.0f; dd[k] = 0.0f; }
    for (int k = i; k < n; k += st)   { cnt[k] = 0; cur[k] = 0; }
}

__global__ void roundx_kernel(const float* __restrict__ X, float* __restrict__ XR,
                              size_t n4) {
    size_t i = (size_t)blockIdx.x * blockDim.x + threadIdx.x;
    size_t st = (size_t)gridDim.x * blockDim.x;
    for (; i < n4; i += st) {
        float4 v = ((const float4*)X)[i];
        v.x = wmma::__float_to_tf32(v.x);
        v.y = wmma::__float_to_tf32(v.y);
        v.z = wmma::__float_to_tf32(v.z);
        v.w = wmma::__float_to_tf32(v.w);
        ((float4*)XR)[i] = v;
    }
}

__global__ void roundw_kernel(const float* __restrict__ W1, const float* __restrict__ W2,
                              float* __restrict__ W1R, float* __restrict__ W2R) {
    int i = blockIdx.x * blockDim.x + threadIdx.x;
    if (i < NREL * 128 * HF)   W1R[i] = wmma::__float_to_tf32(W1[i]);
    if (i < NREL * 128 * OUTF) W2R[i] = wmma::__float_to_tf32(W2[i]);
}

__global__ void degree_kernel(const void* __restrict__ src, const void* __restrict__ dst,
                              float* __restrict__ ds, float* __restrict__ dd,
                              int* __restrict__ cnt, int E, int M) {
    int i = blockIdx.x * blockDim.x + threadIdx.x;
    if (i >= NREL * E) return;
    const int is64 = g_idx64;
    int r = i / E;
    int s = load_idx(src, i, is64);
    int d = load_idx(dst, i, is64);
    atomicAdd(&ds[r * M + s], 1.0f);
    atomicAdd(&dd[r * M + d], 1.0f);
    atomicAdd(&cnt[d], 1);
}

// ---------------------------------------------------------------------------
__device__ __forceinline__ int block_incl_scan(int v, int* wsum) {
    const int lane = threadIdx.x & 31, wid = threadIdx.x >> 5;
    int s = v;
#pragma unroll
    for (int o = 1; o < 32; o <<= 1) {
        int t = __shfl_up_sync(~0u, s, o);
        if (lane >= o) s += t;
    }
    if (lane == 31) wsum[wid] = s;
    __syncthreads();
    if (wid == 0) {
        int ws = (lane < (SCAN_B / 32)) ? wsum[lane] : 0;
#pragma unroll
        for (int o = 1; o < 32; o <<= 1) {
            int t = __shfl_up_sync(~0u, ws, o);
            if (lane >= o) ws += t;
        }
        wsum[lane] = ws;
    }
    __syncthreads();
    return s + (wid > 0 ? wsum[wid - 1] : 0);
}

__global__ void scanA_kernel(const int* __restrict__ cnt, int* __restrict__ bsum, int n) {
    __shared__ int wsum[32];
    int i = blockIdx.x * SCAN_B + threadIdx.x;
    int v = (i < n) ? cnt[i] : 0;
    int s = block_incl_scan(v, wsum);
    if (threadIdx.x == SCAN_B - 1) bsum[blockIdx.x] = s;
}

__global__ void scanB_kernel(const int* __restrict__ bsum, int* __restrict__ boff,
                             int* __restrict__ off, int nb, int n) {
    const int lane = threadIdx.x;
    int carry = 0;
    for (int base = 0; base < nb; base += 32) {
        int i = base + lane;
        int v = (i < nb) ? bsum[i] : 0;
        int s = v;
#pragma unroll
        for (int o = 1; o < 32; o <<= 1) {
            int t = __shfl_up_sync(~0u, s, o);
            if (lane >= o) s += t;
        }
        if (i < nb) boff[i] = carry + s - v;
        carry += __shfl_sync(~0u, s, 31);
    }
    if (lane == 0) off[n] = carry;
}

__global__ void scanC_kernel(const int* __restrict__ cnt, const int* __restrict__ boff,
                             int* __restrict__ off, int n) {
    __shared__ int wsum[32];
    int i = blockIdx.x * SCAN_B + threadIdx.x;
    int v = (i < n) ? cnt[i] : 0;
    int s = block_incl_scan(v, wsum);
    if (i < n) off[i] = boff[blockIdx.x] + s - v;
}

// ---------------------------------------------------------------------------
__global__ void fill_kernel(const void* __restrict__ src, const void* __restrict__ dst,
                            const float* __restrict__ ds, const float* __restrict__ dd,
                            const int* __restrict__ off, int* __restrict__ cur,
                            int2* __restrict__ edge, int E, int M) {
    int i = blockIdx.x * blockDim.x + threadIdx.x;
    if (i >= NREL * E) return;
    const int is64 = g_idx64;
    int r = i / E;
    int s = load_idx(src, i, is64);
    int d = load_idx(dst, i, is64);
    int pos = off[d] + atomicAdd(&cur[d], 1);
    float coef = rsqrtf(fmaxf(ds[r * M + s], 1.0f)) *
                 rsqrtf(fmaxf(dd[r * M + d], 1.0f));
    edge[pos] = make_int2(s | (r << 20), __float_as_int(coef));
}

// ---------------------------------------------------------------------------
// wmma tf32 GEMM. Inputs pre-rounded to tf32 -> raw-bit cp.async staging,
// no in-fragment rounding. fp32 output, direct store_matrix_sync epilogue.
// ---------------------------------------------------------------------------
template <int NF>
__global__ __launch_bounds__(256, 2)
void gemm_kernel(const float* __restrict__ A, const float* __restrict__ B,
                 float* __restrict__ C, int M, int Mp) {
    constexpr int NFRAG = NF / 32;
    constexpr int AST = 36, BST = NF + 4;
    constexpr int ABUF = 128 * AST, BBUF = 32 * BST;
    constexpr int BCH = (32 * NF / 4) / 256;
    extern __shared__ float sm[];
    float* As = sm;
    float* Bs = sm + 2 * ABUF;

    const int r    = blockIdx.y;
    const int row0 = blockIdx.x * 128;
    const int tid  = threadIdx.x;
    const int wid  = tid >> 5;
    const int wm   = wid >> 1;
    const int wn   = wid & 1;
    const float* Br = B + (size_t)r * 128 * NF;

    const int arr = tid >> 1;
    const int acb = (tid & 1) * 16;
    const int gr  = row0 + arr;
    const int asz = (gr < M) ? 16 : 0;
    const float* Arow = A + (size_t)gr * 128 + acb;

    auto stage = [&](int kc, int buf) {
        float* Ab = As + buf * ABUF + arr * AST + acb;
        const float* Ag = Arow + kc * 32;
#pragma unroll
        for (int j = 0; j < 4; j++)
            cp16(Ab + j * 4, Ag + j * 4, asz);
#pragma unroll
        for (int i = 0; i < BCH; i++) {
            int idx = tid + i * 256;
            int rr = idx / (NF / 4);
            int cc = (idx % (NF / 4)) * 4;
            cp16(Bs + buf * BBUF + rr * BST + cc,
                 Br + (size_t)(kc * 32 + rr) * NF + cc);
        }
        CP_COMMIT();
    };

    wmma::fragment<wmma::accumulator, 16, 16, 8, float> acc[2][NFRAG];
#pragma unroll
    for (int m = 0; m < 2; m++)
#pragma unroll
        for (int n = 0; n < NFRAG; n++) wmma::fill_fragment(acc[m][n], 0.0f);

    stage(0, 0);
#pragma unroll
    for (int kc = 0; kc < 4; kc++) {
        const int cur = kc & 1;
        if (kc < 3) {
            stage(kc + 1, cur ^ 1);
            CP_WAIT(1);
        } else {
            CP_WAIT(0);
        }
        __syncthreads();
        const float* Ab = As + cur * ABUF + (wm * 32) * AST;
        const float* Bb = Bs + cur * BBUF + wn * (NF / 2);
#pragma unroll
        for (int kf = 0; kf < 4; kf++) {
            wmma::fragment<wmma::matrix_a, 16, 16, 8, wmma::precision::tf32,
                           wmma::row_major> a0, a1;
            wmma::load_matrix_sync(a0, Ab + kf * 8, AST);
            wmma::load_matrix_sync(a1, Ab + 16 * AST + kf * 8, AST);
#pragma unroll
            for (int n = 0; n < NFRAG; n++) {
                wmma::fragment<wmma::matrix_b, 16, 16, 8, wmma::precision::tf32,
                               wmma::row_major> b;
                wmma::load_matrix_sync(b, Bb + (kf * 8) * BST + n * 16, BST);
                wmma::mma_sync(acc[0][n], a0, b, acc[0][n]);
                wmma::mma_sync(acc[1][n], a1, b, acc[1][n]);
            }
        }
        __syncthreads();
    }

    // epilogue: direct fp32 stores into padded C (Mp rows; no guard)
#pragma unroll
    for (int m = 0; m < 2; m++) {
        float* Crow = C + ((size_t)r * Mp + row0 + wm * 32 + m * 16) * NF
                        + wn * (NF / 2);
#pragma unroll
        for (int n = 0; n < NFRAG; n++)
            wmma::store_matrix_sync(Crow + n * 16, acc[m][n], NF,
                                    wmma::mem_row_major);
    }
}

// ---------------------------------------------------------------------------
// gather1: warp per dst, 128 feats; h = tf32round(relu(agg + b1sum))
__global__ __launch_bounds__(256)
void gather1_kernel(const float* __restrict__ Z, const int* __restrict__ off,
                    const int2* __restrict__ edge,
                    const float* __restrict__ b1, float* __restrict__ h,
                    int M, int Mp) {
    const int d = blockIdx.x * 8 + (threadIdx.x >> 5);
    const int lane = threadIdx.x & 31;
    if (d >= M) return;
    const int e0 = off[d], e1 = off[d + 1];
    float4 acc = make_float4(0.f, 0.f, 0.f, 0.f);
#pragma unroll 8
    for (int e = e0; e < e1; e++) {
        const int2 ed = __ldg(&edge[e]);
        const int s = ed.x & 0xFFFFF, r = ed.x >> 20;
        const float c = __int_as_float(ed.y);
        const float4 v = *(const float4*)(Z + ((size_t)r * Mp + s) * 128 + lane * 4);
        acc.x += c * v.x; acc.y += c * v.y; acc.z += c * v.z; acc.w += c * v.w;
    }
    const int f = lane * 4;
    float4 o;
    o.x = wmma::__float_to_tf32(fmaxf(acc.x + b1[f+0] + b1[128+f+0] + b1[256+f+0] + b1[384+f+0], 0.f));
    o.y = wmma::__float_to_tf32(fmaxf(acc.y + b1[f+1] + b1[128+f+1] + b1[256+f+1] + b1[384+f+1], 0.f));
    o.z = wmma::__float_to_tf32(fmaxf(acc.z + b1[f+2] + b1[128+f+2] + b1[256+f+2] + b1[384+f+2], 0.f));
    o.w = wmma::__float_to_tf32(fmaxf(acc.w + b1[f+3] + b1[128+f+3] + b1[256+f+3] + b1[384+f+3], 0.f));
    *(float4*)(h + (size_t)d * 128 + f) = o;
}

// gather2: half-warp per dst, 64 feats; out = agg + b2sum
__global__ __launch_bounds__(256)
void gather2_kernel(const float* __restrict__ Y, const int* __restrict__ off,
                    const int2* __restrict__ edge,
                    const float* __restrict__ b2, float* __restrict__ out,
                    int M, int Mp) {
    const int warp = blockIdx.x * 8 + (threadIdx.x >> 5);
    const int lane = threadIdx.x & 31;
    const int d = warp * 2 + (lane >> 4);
    const int fl = lane & 15;
    if (d >= M) return;
    const int e0 = off[d], e1 = off[d + 1];
    float4 acc = make_float4(0.f, 0.f, 0.f, 0.f);
#pragma unroll 8
    for (int e = e0; e < e1; e++) {
        const int2 ed = __ldg(&edge[e]);
        const int s = ed.x & 0xFFFFF, r = ed.x >> 20;
        const float c = __int_as_float(ed.y);
        const float4 v = *(const float4*)(Y + ((size_t)r * Mp + s) * 64 + fl * 4);
        acc.x += c * v.x; acc.y += c * v.y; acc.z += c * v.z; acc.w += c * v.w;
    }
    const int f = fl * 4;
    float4 o;
    o.x = acc.x + b2[f+0] + b2[64+f+0] + b2[128+f+0] + b2[192+f+0];
    o.y = acc.y + b2[f+1] + b2[64+f+1] + b2[128+f+1] + b2[192+f+1];
    o.z = acc.z + b2[f+2] + b2[64+f+2] + b2[128+f+2] + b2[192+f+2];
    o.w = acc.w + b2[f+3] + b2[64+f+3] + b2[128+f+3] + b2[192+f+3];
    *(float4*)(out + (size_t)d * 64 + f) = o;
}

// ---------------------------------------------------------------------------
extern "C" void kernel_launch(void* const* d_in, const int* in_sizes, int n_in,
                              void* d_out, int out_size) {
    const float* x    = (const float*)d_in[0];
    const void*  srcI = d_in[1];
    const void*  dstI = d_in[2];
    const float* W1   = (const float*)d_in[3];
    const float* b1   = (const float*)d_in[4];
    const float* W2   = (const float*)d_in[5];
    const float* b2   = (const float*)d_in[6];
    float*       out  = (float*)d_out;

    const int M = in_sizes[0] / INF;
    const int E = in_sizes[1] / NREL;
    const int tiles = (M + 127) / 128;
    const int Mp = tiles * 128;
    const int NB = (M + SCAN_B - 1) / SCAN_B;

    float *z, *y, *h, *xr, *w1r, *w2r, *ds, *dd;
    int *cnt, *off, *cur, *bsum, *boff;
    int2 *edge;
    cudaGetSymbolAddress((void**)&z, g_z);
    cudaGetSymbolAddress((void**)&y, g_y);
    cudaGetSymbolAddress((void**)&h, g_h);
    cudaGetSymbolAddress((void**)&xr, g_xr);
    cudaGetSymbolAddress((void**)&w1r, g_w1r);
    cudaGetSymbolAddress((void**)&w2r, g_w2r);
    cudaGetSymbolAddress((void**)&ds, g_deg_src);
    cudaGetSymbolAddress((void**)&dd, g_deg_dst);
    cudaGetSymbolAddress((void**)&cnt, g_cnt);
    cudaGetSymbolAddress((void**)&off, g_off);
    cudaGetSymbolAddress((void**)&cur, g_cursor);
    cudaGetSymbolAddress((void**)&edge, g_edge);
    cudaGetSymbolAddress((void**)&bsum, g_bsum);
    cudaGetSymbolAddress((void**)&boff, g_boff);

    const int SMEM1 = (2 * 128 * 36 + 2 * 32 * (HF + 4)) * 4;    // 70656
    const int SMEM2 = (2 * 128 * 36 + 2 * 32 * (OUTF + 4)) * 4;  // 54272
    cudaFuncSetAttribute(gemm_kernel<HF>,
                         cudaFuncAttributeMaxDynamicSharedMemorySize, SMEM1);
    cudaFuncSetAttribute(gemm_kernel<OUTF>,
                         cudaFuncAttributeMaxDynamicSharedMemorySize, SMEM2);

    // 1 init (+detect)
    init_kernel<<<512, 256>>>((const unsigned int*)srcI, NREL * E,
                              ds, dd, NREL * M, cnt, cur, M);
    // 2 round x -> xr (tf32 RN)
    roundx_kernel<<<2048, 256>>>(x, xr, (size_t)M * INF / 4);
    // 3 round weights
    roundw_kernel<<<(NREL * 128 * HF + 255) / 256, 256>>>(W1, W2, w1r, w2r);
    // 4 layer-1 GEMM (ncu capture slot)
    {
        dim3 grid(tiles, NREL);
        gemm_kernel<HF><<<grid, 256, SMEM1>>>(xr, w1r, z, M, Mp);
    }
    // 5 degrees + counts
    degree_kernel<<<(NREL * E + 255) / 256, 256>>>(srcI, dstI, ds, dd, cnt, E, M);
    // 6-8 scan
    scanA_kernel<<<NB, SCAN_B>>>(cnt, bsum, M);
    scanB_kernel<<<1, 32>>>(bsum, boff, off, NB, M);
    scanC_kernel<<<NB, SCAN_B>>>(cnt, boff, off, M);
    // 9 fill CSR
    fill_kernel<<<(NREL * E + 255) / 256, 256>>>(srcI, dstI, ds, dd,
                                                 off, cur, edge, E, M);
    // 10 layer-1 gather (+bias+relu+tf32 round)
    gather1_kernel<<<(M + 7) / 8, 256>>>(z, off, edge, b1, h, M, Mp);
    // 11 layer-2 GEMM
    {
        dim3 grid(tiles, NREL);
        gemm_kernel<OUTF><<<grid, 256, SMEM2>>>(h, w2r, y, M, Mp);
    }
    // 12 layer-2 gather (+bias)
    gather2_kernel<<<(M + 15) / 16, 256>>>(y, off, edge, b2, out, M, Mp);
}